// round 1
// baseline (speedup 1.0000x reference)
#include <cuda_runtime.h>
#include <math.h>

#define Bdim 2
#define Hdim 16
#define Sdim 2048
#define Ddim 64

constexpr int TQ = 128;
constexpr int TK = 128;
constexpr int QT_P = 132;   // Qt row pitch (floats), mult of 4 for LDS.128
constexpr int KT_P = 132;
constexpr int VS_P = 68;
constexpr int PS_P = 132;
constexpr int SMEM_FLOATS = 64*QT_P + 64*KT_P + TK*VS_P + TQ*PS_P;

__device__ __forceinline__ unsigned long long dup2(float x) {
    unsigned long long r; unsigned u = __float_as_uint(x);
    asm("mov.b64 %0, {%1,%1};" : "=l"(r) : "r"(u));
    return r;
}
#define FMA2(d,a,b) asm("fma.rn.f32x2 %0,%1,%2,%0;" : "+l"(d) : "l"(a), "l"(b))
#define MUL2(d,b)   asm("mul.rn.f32x2 %0,%0,%1;"    : "+l"(d) : "l"(b))

__device__ __forceinline__ float lo32(unsigned long long v){ return __uint_as_float((unsigned)(v & 0xffffffffull)); }
__device__ __forceinline__ float hi32(unsigned long long v){ return __uint_as_float((unsigned)(v >> 32)); }

__global__ void __launch_bounds__(256, 1) attn_fused_kernel(
    const float* __restrict__ q, const float* __restrict__ k,
    const float* __restrict__ v, const float* __restrict__ mask,
    float* __restrict__ out, float* __restrict__ wgt)
{
    extern __shared__ float sm[];
    float* Qt = sm;                  // [64][QT_P]  transposed Q tile
    float* Kt = Qt + 64*QT_P;        // [64][KT_P]  transposed K tile
    float* Vs = Kt + 64*KT_P;        // [TK][VS_P]  natural V tile
    float* Ps = Vs + TK*VS_P;        // [TQ][PS_P]  P~ tile

    const int t  = threadIdx.x;
    const int tx = t & 15;           // k / d dimension
    const int ty = t >> 4;           // q dimension (8 rows each)
    const int bh = blockIdx.x >> 4;
    const int qt = blockIdx.x & 15;
    const int b  = bh >> 4;          // bh / H
    const int qbase = qt * TQ;

    const float* qp = q + (size_t)bh * Sdim * Ddim;
    const float* kp = k + (size_t)bh * Sdim * Ddim;
    const float* vp = v + (size_t)bh * Sdim * Ddim;
    const float* mp = mask + (size_t)b * Sdim * Sdim;
    float* wp = wgt + (size_t)bh * Sdim * Sdim;
    float* op = out + (size_t)bh * Sdim * Ddim;

    // ---- load Q tile, transposed to Qt[d][q] ----
    #pragma unroll
    for (int rr = 0; rr < 8; ++rr) {
        int row = ty + 16*rr;
        float4 f = *(const float4*)(qp + (size_t)(qbase+row)*Ddim + tx*4);
        int d0 = tx*4;
        Qt[(d0+0)*QT_P + row] = f.x;
        Qt[(d0+1)*QT_P + row] = f.y;
        Qt[(d0+2)*QT_P + row] = f.z;
        Qt[(d0+3)*QT_P + row] = f.w;
    }

    float m_[8], s_[8];
    unsigned long long O2[8][2];   // O accumulator, d-pairs (tx*4 .. tx*4+3)
    #pragma unroll
    for (int i = 0; i < 8; ++i) { m_[i] = -1e30f; s_[i] = 0.f; O2[i][0] = 0ull; O2[i][1] = 0ull; }

    const float scale = 0.125f;           // 1/sqrt(64)
    const float NEG   = -1e9f;

    for (int kt = 0; kt < Sdim/TK; ++kt) {
        const int kbase = kt * TK;
        __syncthreads();
        // ---- load K tile transposed, V tile natural ----
        #pragma unroll
        for (int rr = 0; rr < 8; ++rr) {
            int row = ty + 16*rr;
            float4 f = *(const float4*)(kp + (size_t)(kbase+row)*Ddim + tx*4);
            int d0 = tx*4;
            Kt[(d0+0)*KT_P + row] = f.x;
            Kt[(d0+1)*KT_P + row] = f.y;
            Kt[(d0+2)*KT_P + row] = f.z;
            Kt[(d0+3)*KT_P + row] = f.w;
            float4 g = *(const float4*)(vp + (size_t)(kbase+row)*Ddim + tx*4);
            *(float4*)(Vs + row*VS_P + tx*4) = g;
        }
        __syncthreads();

        // ---- QK^T: 8q x 8k per thread, packed f32x2 over k-pairs ----
        unsigned long long acc[8][4];
        #pragma unroll
        for (int i = 0; i < 8; ++i)
            #pragma unroll
            for (int j = 0; j < 4; ++j) acc[i][j] = 0ull;

        #pragma unroll 2
        for (int d = 0; d < 64; ++d) {
            const float* qr = Qt + d*QT_P + ty*8;
            float4 qa = *(const float4*)qr;
            float4 qb = *(const float4*)(qr+4);
            const float* kr = Kt + d*KT_P + tx*8;
            float4 ka  = *(const float4*)kr;
            float4 kb2 = *(const float4*)(kr+4);
            unsigned long long kk2[4];
            kk2[0] = ((const unsigned long long*)&ka)[0];
            kk2[1] = ((const unsigned long long*)&ka)[1];
            kk2[2] = ((const unsigned long long*)&kb2)[0];
            kk2[3] = ((const unsigned long long*)&kb2)[1];
            float qv[8] = {qa.x,qa.y,qa.z,qa.w,qb.x,qb.y,qb.z,qb.w};
            #pragma unroll
            for (int i = 0; i < 8; ++i) {
                unsigned long long qd = dup2(qv[i]);
                FMA2(acc[i][0], qd, kk2[0]);
                FMA2(acc[i][1], qd, kk2[1]);
                FMA2(acc[i][2], qd, kk2[2]);
                FMA2(acc[i][3], qd, kk2[3]);
            }
        }

        // ---- epilogue: mask, raw-logit write, online softmax, P~ to smem ----
        #pragma unroll
        for (int i = 0; i < 8; ++i) {
            const int qg = qbase + ty*8 + i;
            float l[8];
            #pragma unroll
            for (int j2 = 0; j2 < 4; ++j2) {
                l[2*j2]   = lo32(acc[i][j2]);
                l[2*j2+1] = hi32(acc[i][j2]);
            }
            const float* mrow = mp + (size_t)qg*Sdim + kbase + tx*8;
            float4 ma = __ldg((const float4*)mrow);
            float4 mb = __ldg((const float4*)(mrow+4));
            float mv[8] = {ma.x,ma.y,ma.z,ma.w,mb.x,mb.y,mb.z,mb.w};
            #pragma unroll
            for (int j = 0; j < 8; ++j) l[j] = fmaf(l[j], scale, mv[j]*NEG);

            // raw logits -> weights buffer (normalized in phase 2)
            float* wrow = wp + (size_t)qg*Sdim + kbase + tx*8;
            *(float4*)wrow     = make_float4(l[0],l[1],l[2],l[3]);
            *(float4*)(wrow+4) = make_float4(l[4],l[5],l[6],l[7]);

            float mx = l[0];
            #pragma unroll
            for (int j = 1; j < 8; ++j) mx = fmaxf(mx, l[j]);
            #pragma unroll
            for (int off = 8; off; off >>= 1)
                mx = fmaxf(mx, __shfl_xor_sync(0xffffffffu, mx, off));
            float mnew  = fmaxf(m_[i], mx);
            float alpha = __expf(m_[i] - mnew);
            float p[8], sum = 0.f;
            #pragma unroll
            for (int j = 0; j < 8; ++j) { p[j] = __expf(l[j] - mnew); sum += p[j]; }
            #pragma unroll
            for (int off = 8; off; off >>= 1)
                sum += __shfl_xor_sync(0xffffffffu, sum, off);
            s_[i] = s_[i]*alpha + sum;
            m_[i] = mnew;
            unsigned long long ad = dup2(alpha);
            MUL2(O2[i][0], ad);
            MUL2(O2[i][1], ad);

            float* prow = Ps + (ty*8+i)*PS_P + tx*8;
            *(float4*)prow     = make_float4(p[0],p[1],p[2],p[3]);
            *(float4*)(prow+4) = make_float4(p[4],p[5],p[6],p[7]);
        }
        __syncthreads();

        // ---- PV: O[8q][4d] += P~[q][k] * V[k][d] ----
        #pragma unroll 1
        for (int kc = 0; kc < TK/4; ++kc) {
            int kb = kc*4;
            unsigned long long vf[4][2];
            #pragma unroll
            for (int kk = 0; kk < 4; ++kk) {
                float4 vv = *(const float4*)(Vs + (kb+kk)*VS_P + tx*4);
                vf[kk][0] = ((const unsigned long long*)&vv)[0];
                vf[kk][1] = ((const unsigned long long*)&vv)[1];
            }
            #pragma unroll
            for (int i = 0; i < 8; ++i) {
                float4 pf = *(const float4*)(Ps + (ty*8+i)*PS_P + kb);
                float pv[4] = {pf.x,pf.y,pf.z,pf.w};
                #pragma unroll
                for (int kk = 0; kk < 4; ++kk) {
                    unsigned long long pd = dup2(pv[kk]);
                    FMA2(O2[i][0], pd, vf[kk][0]);
                    FMA2(O2[i][1], pd, vf[kk][1]);
                }
            }
        }
    }

    // ---- write O = O_acc / s ----
    float invs[8];
    #pragma unroll
    for (int i = 0; i < 8; ++i) invs[i] = 1.f / s_[i];

    #pragma unroll
    for (int i = 0; i < 8; ++i) {
        int qg = qbase + ty*8 + i;
        float4 ov = make_float4(lo32(O2[i][0])*invs[i], hi32(O2[i][0])*invs[i],
                                lo32(O2[i][1])*invs[i], hi32(O2[i][1])*invs[i]);
        *(float4*)(op + (size_t)qg*Ddim + tx*4) = ov;
    }

    // ---- phase 2: normalize weights in place (same-thread RAW on own writes) ----
    for (int kt2 = 0; kt2 < Sdim/TK; ++kt2) {
        #pragma unroll
        for (int i = 0; i < 8; ++i) {
            int qg = qbase + ty*8 + i;
            float* wrow = wp + (size_t)qg*Sdim + kt2*TK + tx*8;
            float4 a = *(float4*)wrow;
            float4 c = *(float4*)(wrow+4);
            float mm = m_[i], ii = invs[i];
            a.x = __expf(a.x - mm)*ii; a.y = __expf(a.y - mm)*ii;
            a.z = __expf(a.z - mm)*ii; a.w = __expf(a.w - mm)*ii;
            c.x = __expf(c.x - mm)*ii; c.y = __expf(c.y - mm)*ii;
            c.z = __expf(c.z - mm)*ii; c.w = __expf(c.w - mm)*ii;
            *(float4*)wrow     = a;
            *(float4*)(wrow+4) = c;
        }
    }
}

extern "C" void kernel_launch(void* const* d_in, const int* in_sizes, int n_in,
                              void* d_out, int out_size) {
    const float* q    = (const float*)d_in[0];
    const float* k    = (const float*)d_in[1];
    const float* v    = (const float*)d_in[2];
    const float* mask = (const float*)d_in[3];
    float* out = (float*)d_out;
    float* wgt = out + (size_t)Bdim*Hdim*Sdim*Ddim;   // tuple order: (out, weights)

    int smem_bytes = SMEM_FLOATS * (int)sizeof(float);
    cudaFuncSetAttribute(attn_fused_kernel,
                         cudaFuncAttributeMaxDynamicSharedMemorySize, smem_bytes);
    dim3 grid(Bdim*Hdim*(Sdim/TQ));   // 512 blocks
    attn_fused_kernel<<<grid, 256, smem_bytes>>>(q, k, v, mask, out, wgt);
}

// round 2
// speedup vs baseline: 2.9137x; 2.9137x over previous
#include <cuda_runtime.h>
#include <cuda_fp16.h>
#include <math.h>

#define Bdim 2
#define Hdim 16
#define Sdim 2048
#define Ddim 64

constexpr int TQ = 64;          // q rows per CTA (16 per warp, 4 warps)
constexpr int TK = 128;         // k cols per tile
constexpr int QP = 72;          // half-elem pitches (144B = 16B multiple)
constexpr int KP = 72;
constexpr int VP = 72;
constexpr int SMEM_HALFS = 64*QP + 128*KP + 128*VP;

__device__ __forceinline__ unsigned smaddr(const void* p) {
    return (unsigned)__cvta_generic_to_shared(p);
}
__device__ __forceinline__ void ldsm_x4(unsigned a, unsigned &r0, unsigned &r1, unsigned &r2, unsigned &r3) {
    asm volatile("ldmatrix.sync.aligned.m8n8.x4.shared.b16 {%0,%1,%2,%3}, [%4];"
                 : "=r"(r0), "=r"(r1), "=r"(r2), "=r"(r3) : "r"(a));
}
__device__ __forceinline__ void ldsm_x4_t(unsigned a, unsigned &r0, unsigned &r1, unsigned &r2, unsigned &r3) {
    asm volatile("ldmatrix.sync.aligned.m8n8.x4.trans.shared.b16 {%0,%1,%2,%3}, [%4];"
                 : "=r"(r0), "=r"(r1), "=r"(r2), "=r"(r3) : "r"(a));
}
__device__ __forceinline__ void mma16816(float* c, const unsigned* a, unsigned b0, unsigned b1) {
    asm volatile("mma.sync.aligned.m16n8k16.row.col.f32.f16.f16.f32 "
                 "{%0,%1,%2,%3}, {%4,%5,%6,%7}, {%8,%9}, {%0,%1,%2,%3};"
                 : "+f"(c[0]), "+f"(c[1]), "+f"(c[2]), "+f"(c[3])
                 : "r"(a[0]), "r"(a[1]), "r"(a[2]), "r"(a[3]), "r"(b0), "r"(b1));
}
__device__ __forceinline__ unsigned pack_h2(float x, float y) {
    __half2 h = __floats2half2_rn(x, y);
    return *(unsigned*)&h;
}

__global__ void __launch_bounds__(128, 3) attn_mma_kernel(
    const float* __restrict__ q, const float* __restrict__ k,
    const float* __restrict__ v, const float* __restrict__ mask,
    float* __restrict__ out, float* __restrict__ wgt)
{
    extern __shared__ __half sm[];
    __half* Qh = sm;              // [64][QP]
    __half* Kh = Qh + 64*QP;      // [128][KP]
    __half* Vs = Kh + 128*KP;     // [128][VP]

    const int t    = threadIdx.x;
    const int lane = t & 31;
    const int w    = t >> 5;
    const int bh   = blockIdx.x >> 5;   // S/TQ = 32 qtiles per (b,h)
    const int qt   = blockIdx.x & 31;
    const int b    = bh >> 4;
    const int qbase = qt * TQ;

    const float* qp = q + (size_t)bh * Sdim * Ddim;
    const float* kp = k + (size_t)bh * Sdim * Ddim;
    const float* vp = v + (size_t)bh * Sdim * Ddim;
    const float* mp = mask + (size_t)b * Sdim * Sdim;
    float* wp = wgt + (size_t)bh * Sdim * Sdim;
    float* op = out + (size_t)bh * Sdim * Ddim;

    const float scale = 0.125f;
    const float NEG = -1e9f;

    // ---- load Q tile -> Qh fp16 ----
    {
        const int tx = t & 15, ty = t >> 4;
        #pragma unroll
        for (int i = 0; i < 8; ++i) {
            int row = ty + 8*i;
            float4 f = *(const float4*)(qp + (size_t)(qbase+row)*Ddim + tx*4);
            __half2* dst = (__half2*)(Qh + row*QP + tx*4);
            dst[0] = __floats2half2_rn(f.x, f.y);
            dst[1] = __floats2half2_rn(f.z, f.w);
        }
    }
    __syncthreads();

    // ---- A-fragments of Q (held for entire kernel) ----
    unsigned qa[4][4];
    #pragma unroll
    for (int ks = 0; ks < 4; ++ks) {
        unsigned a = smaddr(Qh + (w*16 + (lane & 15))*QP + ks*16 + (lane >> 4)*8);
        ldsm_x4(a, qa[ks][0], qa[ks][1], qa[ks][2], qa[ks][3]);
    }

    const int qr  = lane >> 2;
    const int qc  = (lane & 3) * 2;
    const int row0 = qbase + w*16 + qr;
    const int row1 = row0 + 8;
    const float* m0p = mp + (size_t)row0 * Sdim;
    const float* m1p = mp + (size_t)row1 * Sdim;

    float m0 = -1e30f, m1 = -1e30f, s0 = 0.f, s1 = 0.f;

    // ================= PASS A: compute m, s only =================
    for (int kt = 0; kt < Sdim/TK; ++kt) {
        const int kbase = kt * TK;
        __syncthreads();
        {
            const int tx = t & 15, ty = t >> 4;
            #pragma unroll
            for (int i = 0; i < 16; ++i) {
                int row = ty + 8*i;
                float4 f = *(const float4*)(kp + (size_t)(kbase+row)*Ddim + tx*4);
                __half2* dst = (__half2*)(Kh + row*KP + tx*4);
                dst[0] = __floats2half2_rn(f.x, f.y);
                dst[1] = __floats2half2_rn(f.z, f.w);
            }
        }
        __syncthreads();

        float sf[16][4];
        #pragma unroll
        for (int nt = 0; nt < 16; ++nt) { sf[nt][0]=0.f; sf[nt][1]=0.f; sf[nt][2]=0.f; sf[nt][3]=0.f; }

        #pragma unroll
        for (int ks = 0; ks < 4; ++ks) {
            #pragma unroll
            for (int nt2 = 0; nt2 < 8; ++nt2) {
                unsigned b0,b1,b2,b3;
                unsigned a = smaddr(Kh + (nt2*16 + (lane & 7) + ((lane >> 4) << 3))*KP
                                       + ks*16 + ((lane >> 3) & 1)*8);
                ldsm_x4(a, b0, b1, b2, b3);
                mma16816(sf[2*nt2],   qa[ks], b0, b1);
                mma16816(sf[2*nt2+1], qa[ks], b2, b3);
            }
        }

        float tm0 = -1e30f, tm1 = -1e30f;
        #pragma unroll
        for (int nt = 0; nt < 16; ++nt) {
            int col = kbase + nt*8 + qc;
            float2 k0 = __ldg((const float2*)(m0p + col));
            float2 k1 = __ldg((const float2*)(m1p + col));
            sf[nt][0] = fmaf(sf[nt][0], scale, k0.x*NEG);
            sf[nt][1] = fmaf(sf[nt][1], scale, k0.y*NEG);
            sf[nt][2] = fmaf(sf[nt][2], scale, k1.x*NEG);
            sf[nt][3] = fmaf(sf[nt][3], scale, k1.y*NEG);
            tm0 = fmaxf(tm0, fmaxf(sf[nt][0], sf[nt][1]));
            tm1 = fmaxf(tm1, fmaxf(sf[nt][2], sf[nt][3]));
        }
        tm0 = fmaxf(tm0, __shfl_xor_sync(0xffffffffu, tm0, 1));
        tm0 = fmaxf(tm0, __shfl_xor_sync(0xffffffffu, tm0, 2));
        tm1 = fmaxf(tm1, __shfl_xor_sync(0xffffffffu, tm1, 1));
        tm1 = fmaxf(tm1, __shfl_xor_sync(0xffffffffu, tm1, 2));
        float mn0 = fmaxf(m0, tm0), mn1 = fmaxf(m1, tm1);

        float sum0 = 0.f, sum1 = 0.f;
        #pragma unroll
        for (int nt = 0; nt < 16; ++nt) {
            sum0 += __expf(sf[nt][0]-mn0) + __expf(sf[nt][1]-mn0);
            sum1 += __expf(sf[nt][2]-mn1) + __expf(sf[nt][3]-mn1);
        }
        sum0 += __shfl_xor_sync(0xffffffffu, sum0, 1);
        sum0 += __shfl_xor_sync(0xffffffffu, sum0, 2);
        sum1 += __shfl_xor_sync(0xffffffffu, sum1, 1);
        sum1 += __shfl_xor_sync(0xffffffffu, sum1, 2);

        s0 = s0*__expf(m0-mn0) + sum0;  m0 = mn0;
        s1 = s1*__expf(m1-mn1) + sum1;  m1 = mn1;
    }

    const float inv0 = 1.f / s0;
    const float inv1 = 1.f / s1;

    // ================= PASS B: recompute, write weights, PV =================
    float of[8][4];
    #pragma unroll
    for (int nt = 0; nt < 8; ++nt) { of[nt][0]=0.f; of[nt][1]=0.f; of[nt][2]=0.f; of[nt][3]=0.f; }

    for (int kt = 0; kt < Sdim/TK; ++kt) {
        const int kbase = kt * TK;
        __syncthreads();
        {
            const int tx = t & 15, ty = t >> 4;
            #pragma unroll
            for (int i = 0; i < 16; ++i) {
                int row = ty + 8*i;
                float4 f = *(const float4*)(kp + (size_t)(kbase+row)*Ddim + tx*4);
                __half2* dk = (__half2*)(Kh + row*KP + tx*4);
                dk[0] = __floats2half2_rn(f.x, f.y);
                dk[1] = __floats2half2_rn(f.z, f.w);
                float4 g = *(const float4*)(vp + (size_t)(kbase+row)*Ddim + tx*4);
                __half2* dv = (__half2*)(Vs + row*VP + tx*4);
                dv[0] = __floats2half2_rn(g.x, g.y);
                dv[1] = __floats2half2_rn(g.z, g.w);
            }
        }
        __syncthreads();

        float sf[16][4];
        #pragma unroll
        for (int nt = 0; nt < 16; ++nt) { sf[nt][0]=0.f; sf[nt][1]=0.f; sf[nt][2]=0.f; sf[nt][3]=0.f; }

        #pragma unroll
        for (int ks = 0; ks < 4; ++ks) {
            #pragma unroll
            for (int nt2 = 0; nt2 < 8; ++nt2) {
                unsigned b0,b1,b2,b3;
                unsigned a = smaddr(Kh + (nt2*16 + (lane & 7) + ((lane >> 4) << 3))*KP
                                       + ks*16 + ((lane >> 3) & 1)*8);
                ldsm_x4(a, b0, b1, b2, b3);
                mma16816(sf[2*nt2],   qa[ks], b0, b1);
                mma16816(sf[2*nt2+1], qa[ks], b2, b3);
            }
        }

        // normalize + write final weights
        #pragma unroll
        for (int nt = 0; nt < 16; ++nt) {
            int col = kbase + nt*8 + qc;
            float2 k0 = __ldg((const float2*)(m0p + col));
            float2 k1 = __ldg((const float2*)(m1p + col));
            float w0 = __expf(fmaf(sf[nt][0], scale, k0.x*NEG) - m0) * inv0;
            float w1 = __expf(fmaf(sf[nt][1], scale, k0.y*NEG) - m0) * inv0;
            float w2 = __expf(fmaf(sf[nt][2], scale, k1.x*NEG) - m1) * inv1;
            float w3 = __expf(fmaf(sf[nt][3], scale, k1.y*NEG) - m1) * inv1;
            *(float2*)(wp + (size_t)row0*Sdim + col) = make_float2(w0, w1);
            *(float2*)(wp + (size_t)row1*Sdim + col) = make_float2(w2, w3);
            sf[nt][0]=w0; sf[nt][1]=w1; sf[nt][2]=w2; sf[nt][3]=w3;
        }

        // pack P into A-fragments (C-frag layout == A-frag layout)
        unsigned pa[8][4];
        #pragma unroll
        for (int ks = 0; ks < 8; ++ks) {
            pa[ks][0] = pack_h2(sf[2*ks][0],   sf[2*ks][1]);
            pa[ks][1] = pack_h2(sf[2*ks][2],   sf[2*ks][3]);
            pa[ks][2] = pack_h2(sf[2*ks+1][0], sf[2*ks+1][1]);
            pa[ks][3] = pack_h2(sf[2*ks+1][2], sf[2*ks+1][3]);
        }

        // PV: O += P * V
        #pragma unroll
        for (int ks = 0; ks < 8; ++ks) {
            #pragma unroll
            for (int nt2 = 0; nt2 < 4; ++nt2) {
                unsigned b0,b1,b2,b3;
                unsigned a = smaddr(Vs + (ks*16 + (lane & 7) + ((lane >> 3) & 1)*8)*VP
                                       + nt2*16 + (lane >> 4)*8);
                ldsm_x4_t(a, b0, b1, b2, b3);
                mma16816(of[2*nt2],   pa[ks], b0, b1);
                mma16816(of[2*nt2+1], pa[ks], b2, b3);
            }
        }
    }

    // ---- write O (already normalized) ----
    #pragma unroll
    for (int nt = 0; nt < 8; ++nt) {
        int col = nt*8 + qc;
        *(float2*)(op + (size_t)row0*Ddim + col) = make_float2(of[nt][0], of[nt][1]);
        *(float2*)(op + (size_t)row1*Ddim + col) = make_float2(of[nt][2], of[nt][3]);
    }
}

extern "C" void kernel_launch(void* const* d_in, const int* in_sizes, int n_in,
                              void* d_out, int out_size) {
    const float* q    = (const float*)d_in[0];
    const float* k    = (const float*)d_in[1];
    const float* v    = (const float*)d_in[2];
    const float* mask = (const float*)d_in[3];
    float* out = (float*)d_out;
    float* wgt = out + (size_t)Bdim*Hdim*Sdim*Ddim;

    int smem_bytes = SMEM_HALFS * (int)sizeof(__half);
    cudaFuncSetAttribute(attn_mma_kernel,
                         cudaFuncAttributeMaxDynamicSharedMemorySize, smem_bytes);
    dim3 grid(Bdim*Hdim*(Sdim/TQ));   // 1024 CTAs
    attn_mma_kernel<<<grid, 128, smem_bytes>>>(q, k, v, mask, out, wgt);
}

// round 3
// speedup vs baseline: 4.2240x; 1.4497x over previous
#include <cuda_runtime.h>
#include <cuda_fp16.h>
#include <math.h>

#define Bdim 2
#define Hdim 16
#define Sdim 2048
#define Ddim 64

constexpr int TQ = 64;
constexpr int TK = 128;
constexpr int QP = 72;          // half-elem pitch (144B)
constexpr int KP = 72;
constexpr int VP = 72;
constexpr int SMEM_HALFS = 64*QP + 128*KP + 128*VP;

// ---- scratch (device globals; no allocation) ----
__device__ __half g_qh[(size_t)Bdim*Hdim*Sdim*Ddim];
__device__ __half g_kh[(size_t)Bdim*Hdim*Sdim*Ddim];
__device__ __half g_vh[(size_t)Bdim*Hdim*Sdim*Ddim];
__device__ unsigned g_mb[(size_t)Bdim*Sdim*Sdim/32];

__device__ __forceinline__ unsigned smaddr(const void* p) {
    return (unsigned)__cvta_generic_to_shared(p);
}
__device__ __forceinline__ void ldsm_x4(unsigned a, unsigned &r0, unsigned &r1, unsigned &r2, unsigned &r3) {
    asm volatile("ldmatrix.sync.aligned.m8n8.x4.shared.b16 {%0,%1,%2,%3}, [%4];"
                 : "=r"(r0), "=r"(r1), "=r"(r2), "=r"(r3) : "r"(a));
}
__device__ __forceinline__ void ldsm_x4_t(unsigned a, unsigned &r0, unsigned &r1, unsigned &r2, unsigned &r3) {
    asm volatile("ldmatrix.sync.aligned.m8n8.x4.trans.shared.b16 {%0,%1,%2,%3}, [%4];"
                 : "=r"(r0), "=r"(r1), "=r"(r2), "=r"(r3) : "r"(a));
}
__device__ __forceinline__ void mma16816(float* c, const unsigned* a, unsigned b0, unsigned b1) {
    asm volatile("mma.sync.aligned.m16n8k16.row.col.f32.f16.f16.f32 "
                 "{%0,%1,%2,%3}, {%4,%5,%6,%7}, {%8,%9}, {%0,%1,%2,%3};"
                 : "+f"(c[0]), "+f"(c[1]), "+f"(c[2]), "+f"(c[3])
                 : "r"(a[0]), "r"(a[1]), "r"(a[2]), "r"(a[3]), "r"(b0), "r"(b1));
}
__device__ __forceinline__ unsigned pack_h2(float x, float y) {
    __half2 h = __floats2half2_rn(x, y);
    return *(unsigned*)&h;
}

// ================= prep kernels =================
__global__ void __launch_bounds__(256) cvt_all(const float* __restrict__ q,
                                               const float* __restrict__ k,
                                               const float* __restrict__ v) {
    size_t i = ((size_t)blockIdx.x*blockDim.x + threadIdx.x)*4;
    float4 a = *(const float4*)(q+i);
    float4 b = *(const float4*)(k+i);
    float4 c = *(const float4*)(v+i);
    __half2* dq = (__half2*)(g_qh+i);
    __half2* dk = (__half2*)(g_kh+i);
    __half2* dv = (__half2*)(g_vh+i);
    dq[0]=__floats2half2_rn(a.x,a.y); dq[1]=__floats2half2_rn(a.z,a.w);
    dk[0]=__floats2half2_rn(b.x,b.y); dk[1]=__floats2half2_rn(b.z,b.w);
    dv[0]=__floats2half2_rn(c.x,c.y); dv[1]=__floats2half2_rn(c.z,c.w);
}

// Bit layout: within each 128-col block blk, lane l reads float4 at col blk*128+l*4;
// word blk*4+j (j=0..3) has bit l = (mask[col blk*128+l*4+j] != 0).
__global__ void __launch_bounds__(256) mask_bits(const float* __restrict__ mask) {
    int gw   = blockIdx.x*(blockDim.x>>5) + (threadIdx.x>>5);
    int lane = threadIdx.x & 31;
    float4 f = ((const float4*)mask)[(size_t)gw*32 + lane];
    unsigned b0 = __ballot_sync(0xffffffffu, f.x != 0.f);
    unsigned b1 = __ballot_sync(0xffffffffu, f.y != 0.f);
    unsigned b2 = __ballot_sync(0xffffffffu, f.z != 0.f);
    unsigned b3 = __ballot_sync(0xffffffffu, f.w != 0.f);
    if (lane == 0) {
        uint4 o = make_uint4(b0, b1, b2, b3);
        *(uint4*)(g_mb + (size_t)gw*4) = o;
    }
}

// ================= main kernel =================
__global__ void __launch_bounds__(128, 3) attn_mma_kernel(
    const float* __restrict__ qf_unused,
    float* __restrict__ out, float* __restrict__ wgt)
{
    extern __shared__ __half sm[];
    __half* Qh = sm;              // [64][QP]
    __half* Kh = Qh + 64*QP;      // [128][KP]
    __half* Vs = Kh + 128*KP;     // [128][VP]

    const int t    = threadIdx.x;
    const int lane = t & 31;
    const int w    = t >> 5;
    const int bh   = blockIdx.x >> 5;
    const int qt   = blockIdx.x & 31;
    const int b    = bh >> 4;
    const int qbase = qt * TQ;

    const __half* qp = g_qh + (size_t)bh * Sdim * Ddim;
    const __half* kp = g_kh + (size_t)bh * Sdim * Ddim;
    const __half* vp = g_vh + (size_t)bh * Sdim * Ddim;
    float* wp = wgt + (size_t)bh * Sdim * Sdim;
    float* op = out + (size_t)bh * Sdim * Ddim;

    const float scale = 0.125f;
    const float NEG = -1e9f;

    // ---- load Q tile (fp16 direct) ----
    {
        const int r0 = t >> 3, cc = (t & 7);
        #pragma unroll
        for (int i = 0; i < 4; ++i) {
            int row = r0 + 16*i;
            uint4 val = *(const uint4*)(qp + (size_t)(qbase+row)*Ddim + cc*8);
            *(uint4*)(Qh + row*QP + cc*8) = val;
        }
    }
    __syncthreads();

    unsigned qa[4][4];
    #pragma unroll
    for (int ks = 0; ks < 4; ++ks) {
        unsigned a = smaddr(Qh + (w*16 + (lane & 15))*QP + ks*16 + (lane >> 4)*8);
        ldsm_x4(a, qa[ks][0], qa[ks][1], qa[ks][2], qa[ks][3]);
    }

    const int qr  = lane >> 2;
    const int qc  = (lane & 3) * 2;
    const int row0 = qbase + w*16 + qr;
    const int row1 = row0 + 8;
    const unsigned* mb0 = g_mb + ((size_t)b*Sdim + row0)*(Sdim/32);
    const unsigned* mb1 = g_mb + ((size_t)b*Sdim + row1)*(Sdim/32);
    const int wsel = qc & 3;          // 0 or 2
    const int bsh  = qc >> 2;         // 0 or 1

    float m0 = -1e30f, m1 = -1e30f, s0 = 0.f, s1 = 0.f;

    // ================= PASS A: m, s =================
    for (int kt = 0; kt < Sdim/TK; ++kt) {
        const int kbase = kt * TK;
        __syncthreads();
        {
            const int r0 = t >> 3, cc = t & 7;
            #pragma unroll
            for (int i = 0; i < 8; ++i) {
                int row = r0 + 16*i;
                uint4 val = *(const uint4*)(kp + (size_t)(kbase+row)*Ddim + cc*8);
                *(uint4*)(Kh + row*KP + cc*8) = val;
            }
        }
        __syncthreads();

        float sf[16][4];
        #pragma unroll
        for (int nt = 0; nt < 16; ++nt) { sf[nt][0]=0.f; sf[nt][1]=0.f; sf[nt][2]=0.f; sf[nt][3]=0.f; }

        #pragma unroll
        for (int ks = 0; ks < 4; ++ks) {
            #pragma unroll
            for (int nt2 = 0; nt2 < 8; ++nt2) {
                unsigned b0,b1,b2,b3;
                unsigned a = smaddr(Kh + (nt2*16 + (lane & 7) + ((lane >> 4) << 3))*KP
                                       + ks*16 + ((lane >> 3) & 1)*8);
                ldsm_x4(a, b0, b1, b2, b3);
                mma16816(sf[2*nt2],   qa[ks], b0, b1);
                mma16816(sf[2*nt2+1], qa[ks], b2, b3);
            }
        }

        uint4 mwa = *(const uint4*)(mb0 + kt*4);
        uint4 mwb = *(const uint4*)(mb1 + kt*4);
        const unsigned* wa = (const unsigned*)&mwa;
        const unsigned* wb = (const unsigned*)&mwb;
        unsigned a0 = wa[wsel]   >> bsh;
        unsigned a1 = wa[wsel+1] >> bsh;
        unsigned c0 = wb[wsel]   >> bsh;
        unsigned c1 = wb[wsel+1] >> bsh;

        float tm0 = -1e30f, tm1 = -1e30f;
        #pragma unroll
        for (int nt = 0; nt < 16; ++nt) {
            sf[nt][0] = sf[nt][0]*scale + (((a0 >> (nt*2)) & 1) ? NEG : 0.f);
            sf[nt][1] = sf[nt][1]*scale + (((a1 >> (nt*2)) & 1) ? NEG : 0.f);
            sf[nt][2] = sf[nt][2]*scale + (((c0 >> (nt*2)) & 1) ? NEG : 0.f);
            sf[nt][3] = sf[nt][3]*scale + (((c1 >> (nt*2)) & 1) ? NEG : 0.f);
            tm0 = fmaxf(tm0, fmaxf(sf[nt][0], sf[nt][1]));
            tm1 = fmaxf(tm1, fmaxf(sf[nt][2], sf[nt][3]));
        }
        tm0 = fmaxf(tm0, __shfl_xor_sync(0xffffffffu, tm0, 1));
        tm0 = fmaxf(tm0, __shfl_xor_sync(0xffffffffu, tm0, 2));
        tm1 = fmaxf(tm1, __shfl_xor_sync(0xffffffffu, tm1, 1));
        tm1 = fmaxf(tm1, __shfl_xor_sync(0xffffffffu, tm1, 2));
        float mn0 = fmaxf(m0, tm0), mn1 = fmaxf(m1, tm1);

        float sum0 = 0.f, sum1 = 0.f;
        #pragma unroll
        for (int nt = 0; nt < 16; ++nt) {
            sum0 += __expf(sf[nt][0]-mn0) + __expf(sf[nt][1]-mn0);
            sum1 += __expf(sf[nt][2]-mn1) + __expf(sf[nt][3]-mn1);
        }
        sum0 += __shfl_xor_sync(0xffffffffu, sum0, 1);
        sum0 += __shfl_xor_sync(0xffffffffu, sum0, 2);
        sum1 += __shfl_xor_sync(0xffffffffu, sum1, 1);
        sum1 += __shfl_xor_sync(0xffffffffu, sum1, 2);

        s0 = s0*__expf(m0-mn0) + sum0;  m0 = mn0;
        s1 = s1*__expf(m1-mn1) + sum1;  m1 = mn1;
    }

    const float inv0 = 1.f / s0;
    const float inv1 = 1.f / s1;

    // ================= PASS B =================
    float of[8][4];
    #pragma unroll
    for (int nt = 0; nt < 8; ++nt) { of[nt][0]=0.f; of[nt][1]=0.f; of[nt][2]=0.f; of[nt][3]=0.f; }

    for (int kt = 0; kt < Sdim/TK; ++kt) {
        const int kbase = kt * TK;
        __syncthreads();
        {
            const int r0 = t >> 3, cc = t & 7;
            #pragma unroll
            for (int i = 0; i < 8; ++i) {
                int row = r0 + 16*i;
                uint4 kv = *(const uint4*)(kp + (size_t)(kbase+row)*Ddim + cc*8);
                *(uint4*)(Kh + row*KP + cc*8) = kv;
                uint4 vv = *(const uint4*)(vp + (size_t)(kbase+row)*Ddim + cc*8);
                *(uint4*)(Vs + row*VP + cc*8) = vv;
            }
        }
        __syncthreads();

        float sf[16][4];
        #pragma unroll
        for (int nt = 0; nt < 16; ++nt) { sf[nt][0]=0.f; sf[nt][1]=0.f; sf[nt][2]=0.f; sf[nt][3]=0.f; }

        #pragma unroll
        for (int ks = 0; ks < 4; ++ks) {
            #pragma unroll
            for (int nt2 = 0; nt2 < 8; ++nt2) {
                unsigned b0,b1,b2,b3;
                unsigned a = smaddr(Kh + (nt2*16 + (lane & 7) + ((lane >> 4) << 3))*KP
                                       + ks*16 + ((lane >> 3) & 1)*8);
                ldsm_x4(a, b0, b1, b2, b3);
                mma16816(sf[2*nt2],   qa[ks], b0, b1);
                mma16816(sf[2*nt2+1], qa[ks], b2, b3);
            }
        }

        uint4 mwa = *(const uint4*)(mb0 + kt*4);
        uint4 mwb = *(const uint4*)(mb1 + kt*4);
        const unsigned* wa = (const unsigned*)&mwa;
        const unsigned* wb = (const unsigned*)&mwb;
        unsigned a0 = wa[wsel]   >> bsh;
        unsigned a1 = wa[wsel+1] >> bsh;
        unsigned c0 = wb[wsel]   >> bsh;
        unsigned c1 = wb[wsel+1] >> bsh;

        #pragma unroll
        for (int nt = 0; nt < 16; ++nt) {
            int col = kbase + nt*8 + qc;
            float w0 = __expf(sf[nt][0]*scale + (((a0 >> (nt*2)) & 1) ? NEG : 0.f) - m0) * inv0;
            float w1 = __expf(sf[nt][1]*scale + (((a1 >> (nt*2)) & 1) ? NEG : 0.f) - m0) * inv0;
            float w2 = __expf(sf[nt][2]*scale + (((c0 >> (nt*2)) & 1) ? NEG : 0.f) - m1) * inv1;
            float w3 = __expf(sf[nt][3]*scale + (((c1 >> (nt*2)) & 1) ? NEG : 0.f) - m1) * inv1;
            *(float2*)(wp + (size_t)row0*Sdim + col) = make_float2(w0, w1);
            *(float2*)(wp + (size_t)row1*Sdim + col) = make_float2(w2, w3);
            sf[nt][0]=w0; sf[nt][1]=w1; sf[nt][2]=w2; sf[nt][3]=w3;
        }

        unsigned pa[8][4];
        #pragma unroll
        for (int ks = 0; ks < 8; ++ks) {
            pa[ks][0] = pack_h2(sf[2*ks][0],   sf[2*ks][1]);
            pa[ks][1] = pack_h2(sf[2*ks][2],   sf[2*ks][3]);
            pa[ks][2] = pack_h2(sf[2*ks+1][0], sf[2*ks+1][1]);
            pa[ks][3] = pack_h2(sf[2*ks+1][2], sf[2*ks+1][3]);
        }

        #pragma unroll
        for (int ks = 0; ks < 8; ++ks) {
            #pragma unroll
            for (int nt2 = 0; nt2 < 4; ++nt2) {
                unsigned b0,b1,b2,b3;
                unsigned a = smaddr(Vs + (ks*16 + (lane & 7) + ((lane >> 3) & 1)*8)*VP
                                       + nt2*16 + (lane >> 4)*8);
                ldsm_x4_t(a, b0, b1, b2, b3);
                mma16816(of[2*nt2],   pa[ks], b0, b1);
                mma16816(of[2*nt2+1], pa[ks], b2, b3);
            }
        }
    }

    #pragma unroll
    for (int nt = 0; nt < 8; ++nt) {
        int col = nt*8 + qc;
        *(float2*)(op + (size_t)row0*Ddim + col) = make_float2(of[nt][0], of[nt][1]);
        *(float2*)(op + (size_t)row1*Ddim + col) = make_float2(of[nt][2], of[nt][3]);
    }
}

extern "C" void kernel_launch(void* const* d_in, const int* in_sizes, int n_in,
                              void* d_out, int out_size) {
    const float* q    = (const float*)d_in[0];
    const float* k    = (const float*)d_in[1];
    const float* v    = (const float*)d_in[2];
    const float* mask = (const float*)d_in[3];
    float* out = (float*)d_out;
    float* wgt = out + (size_t)Bdim*Hdim*Sdim*Ddim;

    // prep: fp16 conversion (4 elems/thread) + mask bitpack (128 cols/warp)
    size_t nqkv = (size_t)Bdim*Hdim*Sdim*Ddim;          // 4M
    cvt_all<<<(unsigned)(nqkv/4/256), 256>>>(q, k, v);
    size_t nwarps = (size_t)Bdim*Sdim*Sdim/128;          // 65536
    mask_bits<<<(unsigned)(nwarps/8), 256>>>(mask);

    int smem_bytes = SMEM_HALFS * (int)sizeof(__half);
    cudaFuncSetAttribute(attn_mma_kernel,
                         cudaFuncAttributeMaxDynamicSharedMemorySize, smem_bytes);
    dim3 grid(Bdim*Hdim*(Sdim/TQ));
    attn_mma_kernel<<<grid, 128, smem_bytes>>>(q, out, wgt);
}

// round 4
// speedup vs baseline: 4.6535x; 1.1017x over previous
#include <cuda_runtime.h>
#include <cuda_fp16.h>
#include <math.h>

#define Bdim 2
#define Hdim 16
#define Sdim 2048
#define Ddim 64

constexpr int TQ = 64;
constexpr int TK = 128;
constexpr int NT = Sdim / TK;   // 16
constexpr int QP = 72;          // pitches in halfs: 144B = 9*16B (cp.async-aligned)
constexpr int KP = 72;
constexpr int VP = 72;
constexpr int SMEM_HALFS = 64*QP + 2*128*KP + 128*VP;

// ---- scratch (device globals; no allocation) ----
__device__ __half g_qh[(size_t)Bdim*Hdim*Sdim*Ddim];
__device__ __half g_kh[(size_t)Bdim*Hdim*Sdim*Ddim];
__device__ __half g_vh[(size_t)Bdim*Hdim*Sdim*Ddim];
__device__ unsigned g_mb[(size_t)Bdim*Sdim*Sdim/32];

__device__ __forceinline__ unsigned smaddr(const void* p) {
    return (unsigned)__cvta_generic_to_shared(p);
}
__device__ __forceinline__ void ldsm_x4(unsigned a, unsigned &r0, unsigned &r1, unsigned &r2, unsigned &r3) {
    asm volatile("ldmatrix.sync.aligned.m8n8.x4.shared.b16 {%0,%1,%2,%3}, [%4];"
                 : "=r"(r0), "=r"(r1), "=r"(r2), "=r"(r3) : "r"(a));
}
__device__ __forceinline__ void ldsm_x4_t(unsigned a, unsigned &r0, unsigned &r1, unsigned &r2, unsigned &r3) {
    asm volatile("ldmatrix.sync.aligned.m8n8.x4.trans.shared.b16 {%0,%1,%2,%3}, [%4];"
                 : "=r"(r0), "=r"(r1), "=r"(r2), "=r"(r3) : "r"(a));
}
__device__ __forceinline__ void mma16816(float* c, const unsigned* a, unsigned b0, unsigned b1) {
    asm volatile("mma.sync.aligned.m16n8k16.row.col.f32.f16.f16.f32 "
                 "{%0,%1,%2,%3}, {%4,%5,%6,%7}, {%8,%9}, {%0,%1,%2,%3};"
                 : "+f"(c[0]), "+f"(c[1]), "+f"(c[2]), "+f"(c[3])
                 : "r"(a[0]), "r"(a[1]), "r"(a[2]), "r"(a[3]), "r"(b0), "r"(b1));
}
__device__ __forceinline__ unsigned pack_h2(float x, float y) {
    __half2 h = __floats2half2_rn(x, y);
    return *(unsigned*)&h;
}
__device__ __forceinline__ float ex2(float x) {
    float r; asm("ex2.approx.f32 %0, %1;" : "=f"(r) : "f"(x)); return r;
}
__device__ __forceinline__ void cp16(__half* dst, const __half* src) {
    unsigned a = smaddr(dst);
    asm volatile("cp.async.cg.shared.global [%0], [%1], 16;" :: "r"(a), "l"(src));
}
#define CP_COMMIT asm volatile("cp.async.commit_group;")
#define CP_WAIT0  asm volatile("cp.async.wait_group 0;")

// issue one 128x64-half tile (16KB) as 8 x 16B per thread
__device__ __forceinline__ void issue_tile(__half* dst, const __half* src, int kbase, int t, int pitch) {
    const int r0 = t >> 3, cc = t & 7;
    #pragma unroll
    for (int i = 0; i < 8; ++i) {
        int row = r0 + 16*i;
        cp16(dst + row*pitch + cc*8, src + (size_t)(kbase+row)*Ddim + cc*8);
    }
}

// ================= prep kernels =================
// q is pre-scaled by 1/sqrt(D) * log2(e) so logits come out in log2 domain
__global__ void __launch_bounds__(256) cvt_all(const float* __restrict__ q,
                                               const float* __restrict__ k,
                                               const float* __restrict__ v) {
    const float qs = 0.18033688011112042f;   // 0.125 * log2(e)
    size_t i = ((size_t)blockIdx.x*blockDim.x + threadIdx.x)*4;
    float4 a = *(const float4*)(q+i);
    float4 b = *(const float4*)(k+i);
    float4 c = *(const float4*)(v+i);
    __half2* dq = (__half2*)(g_qh+i);
    __half2* dk = (__half2*)(g_kh+i);
    __half2* dv = (__half2*)(g_vh+i);
    dq[0]=__floats2half2_rn(a.x*qs,a.y*qs); dq[1]=__floats2half2_rn(a.z*qs,a.w*qs);
    dk[0]=__floats2half2_rn(b.x,b.y);       dk[1]=__floats2half2_rn(b.z,b.w);
    dv[0]=__floats2half2_rn(c.x,c.y);       dv[1]=__floats2half2_rn(c.z,c.w);
}

__global__ void __launch_bounds__(256) mask_bits(const float* __restrict__ mask) {
    int gw   = blockIdx.x*(blockDim.x>>5) + (threadIdx.x>>5);
    int lane = threadIdx.x & 31;
    float4 f = ((const float4*)mask)[(size_t)gw*32 + lane];
    unsigned b0 = __ballot_sync(0xffffffffu, f.x != 0.f);
    unsigned b1 = __ballot_sync(0xffffffffu, f.y != 0.f);
    unsigned b2 = __ballot_sync(0xffffffffu, f.z != 0.f);
    unsigned b3 = __ballot_sync(0xffffffffu, f.w != 0.f);
    if (lane == 0) {
        uint4 o = make_uint4(b0, b1, b2, b3);
        *(uint4*)(g_mb + (size_t)gw*4) = o;
    }
}

// ================= main kernel =================
__global__ void __launch_bounds__(128, 3) attn_mma_kernel(
    float* __restrict__ out, float* __restrict__ wgt)
{
    extern __shared__ __half sm[];
    __half* Qh  = sm;                 // [64][QP]
    __half* Kb0 = Qh + 64*QP;         // [128][KP] x2
    __half* Kb1 = Kb0 + 128*KP;
    __half* Vs  = Kb1 + 128*KP;       // [128][VP]

    const int t    = threadIdx.x;
    const int lane = t & 31;
    const int w    = t >> 5;
    const int bh   = blockIdx.x >> 5;
    const int qt   = blockIdx.x & 31;
    const int b    = bh >> 4;
    const int qbase = qt * TQ;

    const __half* qp = g_qh + (size_t)bh * Sdim * Ddim;
    const __half* kp = g_kh + (size_t)bh * Sdim * Ddim;
    const __half* vp = g_vh + (size_t)bh * Sdim * Ddim;
    float* wp = wgt + (size_t)bh * Sdim * Sdim;
    float* op = out + (size_t)bh * Sdim * Ddim;

    const float NEG2 = -1.4426950408889634e9f;   // -1e9 * log2(e)

    // ---- Q tile via cp.async (64 rows) ----
    {
        const int r0 = t >> 3, cc = t & 7;
        #pragma unroll
        for (int i = 0; i < 4; ++i) {
            int row = r0 + 16*i;
            cp16(Qh + row*QP + cc*8, qp + (size_t)(qbase+row)*Ddim + cc*8);
        }
    }
    // prologue: K[0]
    issue_tile(Kb0, kp, 0, t, KP);
    CP_COMMIT; CP_WAIT0;
    __syncthreads();

    unsigned qa[4][4];
    #pragma unroll
    for (int ks = 0; ks < 4; ++ks) {
        unsigned a = smaddr(Qh + (w*16 + (lane & 15))*QP + ks*16 + (lane >> 4)*8);
        ldsm_x4(a, qa[ks][0], qa[ks][1], qa[ks][2], qa[ks][3]);
    }

    const int qr  = lane >> 2;
    const int qc  = (lane & 3) * 2;
    const int row0 = qbase + w*16 + qr;
    const int row1 = row0 + 8;
    const unsigned* mb0 = g_mb + ((size_t)b*Sdim + row0)*(Sdim/32);
    const unsigned* mb1 = g_mb + ((size_t)b*Sdim + row1)*(Sdim/32);
    const int wsel = qc & 3;
    const int bsh  = qc >> 2;

    float m0 = -1e30f, m1 = -1e30f, s0 = 0.f, s1 = 0.f;

    // ================= PASS A: m, s (log2 domain) =================
    for (int kt = 0; kt < NT; ++kt) {
        __half* kc = (kt & 1) ? Kb1 : Kb0;
        if (kt+1 < NT) issue_tile((kt & 1) ? Kb0 : Kb1, kp, (kt+1)*TK, t, KP);
        CP_COMMIT;

        float sf[16][4];
        #pragma unroll
        for (int nt = 0; nt < 16; ++nt) { sf[nt][0]=0.f; sf[nt][1]=0.f; sf[nt][2]=0.f; sf[nt][3]=0.f; }

        #pragma unroll
        for (int ks = 0; ks < 4; ++ks) {
            #pragma unroll
            for (int nt2 = 0; nt2 < 8; ++nt2) {
                unsigned b0,b1,b2,b3;
                unsigned a = smaddr(kc + (nt2*16 + (lane & 7) + ((lane >> 4) << 3))*KP
                                       + ks*16 + ((lane >> 3) & 1)*8);
                ldsm_x4(a, b0, b1, b2, b3);
                mma16816(sf[2*nt2],   qa[ks], b0, b1);
                mma16816(sf[2*nt2+1], qa[ks], b2, b3);
            }
        }

        uint4 mwa = *(const uint4*)(mb0 + kt*4);
        uint4 mwb = *(const uint4*)(mb1 + kt*4);
        const unsigned* wa = (const unsigned*)&mwa;
        const unsigned* wb = (const unsigned*)&mwb;
        unsigned a0 = wa[wsel]   >> bsh;
        unsigned a1 = wa[wsel+1] >> bsh;
        unsigned c0 = wb[wsel]   >> bsh;
        unsigned c1 = wb[wsel+1] >> bsh;

        float tm0 = -1e30f, tm1 = -1e30f;
        #pragma unroll
        for (int nt = 0; nt < 16; ++nt) {
            sf[nt][0] += ((a0 >> (nt*2)) & 1) ? NEG2 : 0.f;
            sf[nt][1] += ((a1 >> (nt*2)) & 1) ? NEG2 : 0.f;
            sf[nt][2] += ((c0 >> (nt*2)) & 1) ? NEG2 : 0.f;
            sf[nt][3] += ((c1 >> (nt*2)) & 1) ? NEG2 : 0.f;
            tm0 = fmaxf(tm0, fmaxf(sf[nt][0], sf[nt][1]));
            tm1 = fmaxf(tm1, fmaxf(sf[nt][2], sf[nt][3]));
        }
        tm0 = fmaxf(tm0, __shfl_xor_sync(0xffffffffu, tm0, 1));
        tm0 = fmaxf(tm0, __shfl_xor_sync(0xffffffffu, tm0, 2));
        tm1 = fmaxf(tm1, __shfl_xor_sync(0xffffffffu, tm1, 1));
        tm1 = fmaxf(tm1, __shfl_xor_sync(0xffffffffu, tm1, 2));
        float mn0 = fmaxf(m0, tm0), mn1 = fmaxf(m1, tm1);

        float sum0 = 0.f, sum1 = 0.f;
        #pragma unroll
        for (int nt = 0; nt < 16; ++nt) {
            sum0 += ex2(sf[nt][0]-mn0) + ex2(sf[nt][1]-mn0);
            sum1 += ex2(sf[nt][2]-mn1) + ex2(sf[nt][3]-mn1);
        }
        sum0 += __shfl_xor_sync(0xffffffffu, sum0, 1);
        sum0 += __shfl_xor_sync(0xffffffffu, sum0, 2);
        sum1 += __shfl_xor_sync(0xffffffffu, sum1, 1);
        sum1 += __shfl_xor_sync(0xffffffffu, sum1, 2);

        s0 = s0*ex2(m0-mn0) + sum0;  m0 = mn0;
        s1 = s1*ex2(m1-mn1) + sum1;  m1 = mn1;

        CP_WAIT0;
        __syncthreads();
    }

    const float inv0 = 1.f / s0;
    const float inv1 = 1.f / s1;

    // ================= PASS B: recompute, write weights, PV =================
    float of[8][4];
    #pragma unroll
    for (int nt = 0; nt < 8; ++nt) { of[nt][0]=0.f; of[nt][1]=0.f; of[nt][2]=0.f; of[nt][3]=0.f; }

    issue_tile(Kb0, kp, 0, t, KP);
    CP_COMMIT; CP_WAIT0;
    __syncthreads();

    for (int kt = 0; kt < NT; ++kt) {
        const int kbase = kt * TK;
        __half* kc = (kt & 1) ? Kb1 : Kb0;
        if (kt+1 < NT) issue_tile((kt & 1) ? Kb0 : Kb1, kp, (kt+1)*TK, t, KP);
        issue_tile(Vs, vp, kbase, t, VP);
        CP_COMMIT;

        float sf[16][4];
        #pragma unroll
        for (int nt = 0; nt < 16; ++nt) { sf[nt][0]=0.f; sf[nt][1]=0.f; sf[nt][2]=0.f; sf[nt][3]=0.f; }

        #pragma unroll
        for (int ks = 0; ks < 4; ++ks) {
            #pragma unroll
            for (int nt2 = 0; nt2 < 8; ++nt2) {
                unsigned b0,b1,b2,b3;
                unsigned a = smaddr(kc + (nt2*16 + (lane & 7) + ((lane >> 4) << 3))*KP
                                       + ks*16 + ((lane >> 3) & 1)*8);
                ldsm_x4(a, b0, b1, b2, b3);
                mma16816(sf[2*nt2],   qa[ks], b0, b1);
                mma16816(sf[2*nt2+1], qa[ks], b2, b3);
            }
        }

        uint4 mwa = *(const uint4*)(mb0 + kt*4);
        uint4 mwb = *(const uint4*)(mb1 + kt*4);
        const unsigned* wa = (const unsigned*)&mwa;
        const unsigned* wb = (const unsigned*)&mwb;
        unsigned a0 = wa[wsel]   >> bsh;
        unsigned a1 = wa[wsel+1] >> bsh;
        unsigned c0 = wb[wsel]   >> bsh;
        unsigned c1 = wb[wsel+1] >> bsh;

        #pragma unroll
        for (int nt = 0; nt < 16; ++nt) {
            int col = kbase + nt*8 + qc;
            float w0 = ex2(sf[nt][0] + (((a0 >> (nt*2)) & 1) ? NEG2 : 0.f) - m0) * inv0;
            float w1 = ex2(sf[nt][1] + (((a1 >> (nt*2)) & 1) ? NEG2 : 0.f) - m0) * inv0;
            float w2 = ex2(sf[nt][2] + (((c0 >> (nt*2)) & 1) ? NEG2 : 0.f) - m1) * inv1;
            float w3 = ex2(sf[nt][3] + (((c1 >> (nt*2)) & 1) ? NEG2 : 0.f) - m1) * inv1;
            *(float2*)(wp + (size_t)row0*Sdim + col) = make_float2(w0, w1);
            *(float2*)(wp + (size_t)row1*Sdim + col) = make_float2(w2, w3);
            sf[nt][0]=w0; sf[nt][1]=w1; sf[nt][2]=w2; sf[nt][3]=w3;
        }

        unsigned pa[8][4];
        #pragma unroll
        for (int ks = 0; ks < 8; ++ks) {
            pa[ks][0] = pack_h2(sf[2*ks][0],   sf[2*ks][1]);
            pa[ks][1] = pack_h2(sf[2*ks][2],   sf[2*ks][3]);
            pa[ks][2] = pack_h2(sf[2*ks+1][0], sf[2*ks+1][1]);
            pa[ks][3] = pack_h2(sf[2*ks+1][2], sf[2*ks+1][3]);
        }

        CP_WAIT0;
        __syncthreads();

        #pragma unroll
        for (int ks = 0; ks < 8; ++ks) {
            #pragma unroll
            for (int nt2 = 0; nt2 < 4; ++nt2) {
                unsigned b0,b1,b2,b3;
                unsigned a = smaddr(Vs + (ks*16 + (lane & 7) + ((lane >> 3) & 1)*8)*VP
                                       + nt2*16 + (lane >> 4)*8);
                ldsm_x4_t(a, b0, b1, b2, b3);
                mma16816(of[2*nt2],   pa[ks], b0, b1);
                mma16816(of[2*nt2+1], pa[ks], b2, b3);
            }
        }
        __syncthreads();
    }

    #pragma unroll
    for (int nt = 0; nt < 8; ++nt) {
        int col = nt*8 + qc;
        *(float2*)(op + (size_t)row0*Ddim + col) = make_float2(of[nt][0], of[nt][1]);
        *(float2*)(op + (size_t)row1*Ddim + col) = make_float2(of[nt][2], of[nt][3]);
    }
}

extern "C" void kernel_launch(void* const* d_in, const int* in_sizes, int n_in,
                              void* d_out, int out_size) {
    const float* q    = (const float*)d_in[0];
    const float* k    = (const float*)d_in[1];
    const float* v    = (const float*)d_in[2];
    const float* mask = (const float*)d_in[3];
    float* out = (float*)d_out;
    float* wgt = out + (size_t)Bdim*Hdim*Sdim*Ddim;

    size_t nqkv = (size_t)Bdim*Hdim*Sdim*Ddim;
    cvt_all<<<(unsigned)(nqkv/4/256), 256>>>(q, k, v);
    size_t nwarps = (size_t)Bdim*Sdim*Sdim/128;
    mask_bits<<<(unsigned)(nwarps/8), 256>>>(mask);

    int smem_bytes = SMEM_HALFS * (int)sizeof(__half);
    cudaFuncSetAttribute(attn_mma_kernel,
                         cudaFuncAttributeMaxDynamicSharedMemorySize, smem_bytes);
    dim3 grid(Bdim*Hdim*(Sdim/TQ));
    attn_mma_kernel<<<grid, 128, smem_bytes>>>(out, wgt);
}